// round 2
// baseline (speedup 1.0000x reference)
#include <cuda_runtime.h>

// Profile-HMM forward NLL + KLD, wavefront (anti-diagonal) formulation.
// 4 batch elements per 128-thread block (one warp each) so warps spread
// across all 4 SMSPs. Lane owns k = 2*lane+1, 2*lane+2. All log values in
// base-2 so logaddexp = fmax + lg2(1+ex2(d)).

#define FULLMASK 0xffffffffu
#define LOG2E 1.4426950408889634f
#define LN2   0.69314718055994531f
#define NEG2  (-144.26950408889634f)   /* -100 * log2(e) */

__device__ float g_vb[512];
__device__ unsigned int g_cnt = 0;

__device__ __forceinline__ float fexp2(float x) {
    float r; asm("ex2.approx.f32 %0, %1;" : "=f"(r) : "f"(x)); return r;
}
__device__ __forceinline__ float flog2(float x) {
    float r; asm("lg2.approx.f32 %0, %1;" : "=f"(r) : "f"(x)); return r;
}
// base-2 logaddexp: log2(2^x + 2^y)
__device__ __forceinline__ float laexp2(float x, float y) {
    float m = fmaxf(x, y);
    float d = fminf(x, y) - m;          // <= 0
    return m + flog2(1.0f + fexp2(d));
}
// base-2 3-way logsumexp
__device__ __forceinline__ float lse3(float x, float y, float z) {
    float m = fmaxf(fmaxf(x, y), z);
    return m + flog2(fexp2(x - m) + fexp2(y - m) + fexp2(z - m));
}

__global__ void __launch_bounds__(128) phmm_kernel(
    const int*   __restrict__ binput,    // (B, 256)
    const float* __restrict__ trans,     // (B, 65, 7)
    const float* __restrict__ emis,      // (B, 64, 4)
    const float* __restrict__ mus,       // (B, 16)
    const float* __restrict__ logvars,   // (B, 16)
    float*       __restrict__ out)
{
    constexpr int L = 256;
    constexpr int K = 64;
    const int warp = threadIdx.x >> 5;
    const int lane = threadIdx.x & 31;
    const int b    = blockIdx.x * 4 + warp;

    __shared__ int s_c[4][L];
    const int* bi = binput + b * L;
#pragma unroll
    for (int i = 0; i < L / 32; ++i) s_c[warp][lane + 32 * i] = bi[lane + 32 * i];
    __syncwarp();

    const float* a  = trans + b * 65 * 7;
    const float* em = emis  + b * 64 * 4;

    const int k1 = 2 * lane + 1;                // slot1 owns k1, slot2 owns k1+1
    const float* r0 = a + (k1 - 1) * 7;         // transition row k1-1
    const float* r1 = r0 + 7;                   // row k1   (= row k2-1)
    const float* r2 = r1 + 7;                   // row k2

    // indices: M2M=0, M2I=1, M2D=2, I2M=3, I2I=4, D2M=5, D2D=6
    const float aMM1 = r0[0] * LOG2E, aMD1 = r0[2] * LOG2E;
    const float aIM1 = r0[3] * LOG2E, aDM1 = r0[5] * LOG2E, aDD1 = r0[6] * LOG2E;
    const float aMI1 = r1[1] * LOG2E, aII1 = r1[4] * LOG2E;
    const float aMM2 = r1[0] * LOG2E, aMD2 = r1[2] * LOG2E;
    const float aIM2 = r1[3] * LOG2E, aDM2 = r1[5] * LOG2E, aDD2 = r1[6] * LOG2E;
    const float aMI2 = r2[1] * LOG2E, aII2 = r2[4] * LOG2E;
    const float aMI0 = a[1]  * LOG2E, aII0 = a[4]  * LOG2E;   // row 0 (k=0 column)

    const float* eb1 = em + (k1 - 1) * 4;
    const float* eb2 = em + k1 * 4;
    const float e10 = eb1[0] * LOG2E, e11 = eb1[1] * LOG2E;
    const float e12 = eb1[2] * LOG2E, e13 = eb1[3] * LOG2E;
    const float e20 = eb2[0] * LOG2E, e21 = eb2[1] * LOG2E;
    const float e22 = eb2[2] * LOG2E, e23 = eb2[3] * LOG2E;

    // state registers: cur = this k's cell on diag t-1, prev = diag t-2
    float cM1 = NEG2, cI1 = NEG2, cD1 = NEG2, pM1 = NEG2, pI1 = NEG2, pD1 = NEG2;
    float cM2 = NEG2, cI2 = NEG2, cD2 = NEG2, pM2 = NEG2, pI2 = NEG2, pD2 = NEG2;
    // k=0 column (replicated on all lanes): M(0,0)=0 (base-2 of 1.0), I(0,0)=NEG
    float k0cM = 0.0f, k0cI = NEG2, k0pM = NEG2, k0pI = NEG2;

    int cprev = s_c[warp][0]; // slot2's symbol == slot1's symbol one diag earlier

#pragma unroll 4
    for (int t = 1; t <= L + K; ++t) {
        // neighbor (k-1) values: lane-1's slot2; lane0's neighbor is the k=0 column
        float nM = __shfl_up_sync(FULLMASK, cM2, 1);   // M(l, k-1)   diag t-1
        float nD = __shfl_up_sync(FULLMASK, cD2, 1);   // D(l, k-1)   diag t-1
        float qM = __shfl_up_sync(FULLMASK, pM2, 1);   // M(l-1, k-1) diag t-2
        float qI = __shfl_up_sync(FULLMASK, pI2, 1);
        float qD = __shfl_up_sync(FULLMASK, pD2, 1);
        if (lane == 0) { nM = k0cM; nD = NEG2; qM = k0pM; qI = k0pI; qD = NEG2; }

        const int l1 = t - k1;
        const int l2 = l1 - 1;

        int ci = l1 - 1;
        ci = ci < 0 ? 0 : (ci > L - 1 ? L - 1 : ci);
        const int c1 = s_c[warp][ci];
        const float e1 = (c1 & 2)    ? ((c1 & 1)    ? e13 : e12) : ((c1 & 1)    ? e11 : e10);
        const float e2 = (cprev & 2) ? ((cprev & 1) ? e23 : e22) : ((cprev & 1) ? e21 : e20);

        // ---- slot1: cell (l1, k1) ----
        float M1g = e1 + lse3(aMM1 + qM, aIM1 + qI, aDM1 + qD);
        float I1g = -2.0f + laexp2(aMI1 + cM1, aII1 + cI1);     // LOG_Q base2 = -2
        float D1n = laexp2(aMD1 + nM, aDD1 + nD);
        float M1n = (l1 == 0) ? NEG2 : M1g;
        float I1n = (l1 == 0) ? NEG2 : I1g;

        // ---- slot2: cell (l2, k2); neighbor is own (old) slot1 ----
        float M2g = e2 + lse3(aMM2 + pM1, aIM2 + pI1, aDM2 + pD1);
        float I2g = -2.0f + laexp2(aMI2 + cM2, aII2 + cI2);
        float D2n = laexp2(aMD2 + cM1, aDD2 + cD1);
        float M2n = (l2 == 0) ? NEG2 : M2g;
        float I2n = (l2 == 0) ? NEG2 : I2g;

        // ---- k=0 column, cell (t, 0): M=NEG for l>=1, D=NEG always ----
        float k0In = -2.0f + laexp2(aMI0 + k0cM, aII0 + k0cI);
        k0pM = k0cM; k0pI = k0cI; k0cM = NEG2; k0cI = k0In;

        // rotate only while the cell is in range (freeze afterwards so the
        // k+1 neighbor can still read the final cur/prev pair once)
        if ((unsigned)l2 <= (unsigned)L) {
            pM2 = cM2; pI2 = cI2; pD2 = cD2; cM2 = M2n; cI2 = I2n; cD2 = D2n;
        }
        if ((unsigned)l1 <= (unsigned)L) {
            pM1 = cM1; pI1 = cI1; pD1 = cD1; cM1 = M1n; cI1 = I1n; cD1 = D1n;
        }
        cprev = c1;
    }

    // lane 31 slot2 holds (M, I, D) at (L, K); broadcast to all lanes
    const float MF = __shfl_sync(FULLMASK, cM2, 31);
    const float IF = __shfl_sync(FULLMASK, cI2, 31);
    const float DF = __shfl_sync(FULLMASK, cD2, 31);
    const float lse = lse3(MF + a[K * 7 + 0] * LOG2E,
                           IF + a[K * 7 + 3] * LOG2E,
                           DF + a[K * 7 + 5] * LOG2E);
    const float nll = -lse * LN2;

    // KLD term: -0.5 * sum_e (1 + lv - mu^2 - exp(lv))
    float term = 0.0f;
    if (lane < 16) {
        const float mu = mus[b * 16 + lane];
        const float lv = logvars[b * 16 + lane];
        term = 1.0f + lv - mu * mu - expf(lv);
    }
#pragma unroll
    for (int o = 16; o > 0; o >>= 1) term += __shfl_xor_sync(FULLMASK, term, o);

    if (lane == 0) g_vb[b] = nll - 0.5f * term;

    // ---- last-block-done final reduction (deterministic fixed-order sum) ----
    __shared__ bool s_last;
    __syncthreads();
    __threadfence();
    if (threadIdx.x == 0) {
        unsigned int old = atomicAdd(&g_cnt, 1u);
        s_last = (old == gridDim.x - 1);
    }
    __syncthreads();
    if (s_last) {
        __threadfence();
        const int t = threadIdx.x;
        __shared__ float sh[128];
        float s = g_vb[t] + g_vb[t + 128] + g_vb[t + 256] + g_vb[t + 384];
        sh[t] = s;
        __syncthreads();
#pragma unroll
        for (int o = 64; o >= 1; o >>= 1) {
            if (t < o) sh[t] += sh[t + o];
            __syncthreads();
        }
        if (t == 0) { out[0] = sh[0] * (1.0f / 512.0f); g_cnt = 0; }
    }
}

extern "C" void kernel_launch(void* const* d_in, const int* in_sizes, int n_in,
                              void* d_out, int out_size) {
    const int*   batch_input = (const int*)  d_in[0];
    const float* trans       = (const float*)d_in[1];
    const float* emisp       = (const float*)d_in[2];
    const float* mus         = (const float*)d_in[3];
    const float* logvars     = (const float*)d_in[4];
    (void)in_sizes; (void)n_in; (void)out_size;

    phmm_kernel<<<128, 128>>>(batch_input, trans, emisp, mus, logvars, (float*)d_out);
}

// round 3
// speedup vs baseline: 2.9048x; 2.9048x over previous
#include <cuda_runtime.h>

// Profile-HMM forward NLL + KLD, wavefront (anti-diagonal) formulation.
// 512 one-warp blocks (one batch element per warp). Lane owns k = 2*lane+1
// and 2*lane+2. All log values kept in base-2. Rotation is UNCONDITIONAL
// (no in-range freeze): consumers at l<=L only ever read producer cells at
// the same l<=L, and pre-wave garbage is flushed by the l==0 forcing.

#define FULLMASK 0xffffffffu
#define LOG2E 1.4426950408889634f
#define LN2   0.69314718055994531f
#define NEG2  (-144.26950408889634f)   /* -100 * log2(e) */

__device__ float g_vb[512];
__device__ unsigned int g_cnt = 0;

__device__ __forceinline__ float fexp2(float x) {
    float r; asm("ex2.approx.f32 %0, %1;" : "=f"(r) : "f"(x)); return r;
}
__device__ __forceinline__ float flog2(float x) {
    float r; asm("lg2.approx.f32 %0, %1;" : "=f"(r) : "f"(x)); return r;
}
// base-2 logaddexp
__device__ __forceinline__ float laexp2(float x, float y) {
    float m = fmaxf(x, y);
    float d = fminf(x, y) - m;          // <= 0
    return m + flog2(1.0f + fexp2(d));
}
// base-2 3-way logsumexp
__device__ __forceinline__ float lse3(float x, float y, float z) {
    float m = fmaxf(fmaxf(x, y), z);
    return m + flog2(fexp2(x - m) + fexp2(y - m) + fexp2(z - m));
}

__global__ void __launch_bounds__(32) phmm_kernel(
    const int*   __restrict__ binput,    // (B, 256)
    const float* __restrict__ trans,     // (B, 65, 7)
    const float* __restrict__ emis,      // (B, 64, 4)
    const float* __restrict__ mus,       // (B, 16)
    const float* __restrict__ logvars,   // (B, 16)
    float*       __restrict__ out)
{
    constexpr int L = 256;
    constexpr int K = 64;
    const int b    = blockIdx.x;
    const int lane = threadIdx.x;

    __shared__ int s_c[320];             // padded: indices up to 318 read garbage-safe 0
    const int* bi = binput + b * L;
#pragma unroll
    for (int i = 0; i < L / 32; ++i) s_c[lane + 32 * i] = bi[lane + 32 * i];
    s_c[256 + lane] = 0;
    s_c[288 + lane] = 0;
    __syncwarp();

    const float* a  = trans + b * 65 * 7;
    const float* em = emis  + b * 64 * 4;

    const int k1 = 2 * lane + 1;                // slot1 owns k1, slot2 owns k1+1
    const float* r0 = a + (k1 - 1) * 7;         // transition row k1-1
    const float* r1 = r0 + 7;                   // row k1   (= row k2-1)
    const float* r2 = r1 + 7;                   // row k2

    // indices: M2M=0, M2I=1, M2D=2, I2M=3, I2I=4, D2M=5, D2D=6
    // LOG_Q in base-2 = -2 is folded into the aMI/aII coefficients.
    const float aMM1 = r0[0] * LOG2E, aMD1 = r0[2] * LOG2E;
    const float aIM1 = r0[3] * LOG2E, aDM1 = r0[5] * LOG2E, aDD1 = r0[6] * LOG2E;
    const float aMI1 = r1[1] * LOG2E - 2.0f, aII1 = r1[4] * LOG2E - 2.0f;
    const float aMM2 = r1[0] * LOG2E, aMD2 = r1[2] * LOG2E;
    const float aIM2 = r1[3] * LOG2E, aDM2 = r1[5] * LOG2E, aDD2 = r1[6] * LOG2E;
    const float aMI2 = r2[1] * LOG2E - 2.0f, aII2 = r2[4] * LOG2E - 2.0f;
    const float aMI0 = a[1]  * LOG2E - 2.0f, aII0 = a[4]  * LOG2E - 2.0f;  // row 0

    const float* eb1 = em + (k1 - 1) * 4;
    const float* eb2 = em + k1 * 4;
    const float e10 = eb1[0] * LOG2E, e11 = eb1[1] * LOG2E;
    const float e12 = eb1[2] * LOG2E, e13 = eb1[3] * LOG2E;
    const float e20 = eb2[0] * LOG2E, e21 = eb2[1] * LOG2E;
    const float e22 = eb2[2] * LOG2E, e23 = eb2[3] * LOG2E;

    // state registers: cur = this k's cell on diag t-1, prev = diag t-2
    float cM1 = NEG2, cI1 = NEG2, cD1 = NEG2, pM1 = NEG2, pI1 = NEG2, pD1 = NEG2;
    float cM2 = NEG2, cI2 = NEG2, cD2 = NEG2, pM2 = NEG2, pI2 = NEG2, pD2 = NEG2;
    // k=0 column (replicated on all lanes): M(0,0)=0, I(0,0)=NEG
    float k0cM = 0.0f, k0cI = NEG2, k0pM = NEG2, k0pI = NEG2;

    int cprev = s_c[0];   // slot2's symbol == slot1's symbol one diag earlier

#pragma unroll 4
    for (int t = 1; t <= L + K; ++t) {
        // neighbor (k-1) values: lane-1's slot2; lane0's neighbor is the k=0 column
        float nM = __shfl_up_sync(FULLMASK, cM2, 1);   // M(l, k-1)   diag t-1
        float nD = __shfl_up_sync(FULLMASK, cD2, 1);   // D(l, k-1)   diag t-1
        float qM = __shfl_up_sync(FULLMASK, pM2, 1);   // M(l-1, k-1) diag t-2
        float qI = __shfl_up_sync(FULLMASK, pI2, 1);
        float qD = __shfl_up_sync(FULLMASK, pD2, 1);
        if (lane == 0) { nM = k0cM; nD = NEG2; qM = k0pM; qI = k0pI; qD = NEG2; }

        const int l1 = t - k1;
        const int l2 = l1 - 1;

        const int c1 = s_c[max(l1 - 1, 0)];
        const float e1 = (c1 & 2)    ? ((c1 & 1)    ? e13 : e12) : ((c1 & 1)    ? e11 : e10);
        const float e2 = (cprev & 2) ? ((cprev & 1) ? e23 : e22) : ((cprev & 1) ? e21 : e20);

        // ---- slot1: cell (l1, k1) ----
        float M1g = e1 + lse3(aMM1 + qM, aIM1 + qI, aDM1 + qD);
        float I1g = laexp2(aMI1 + cM1, aII1 + cI1);
        float D1n = laexp2(aMD1 + nM, aDD1 + nD);
        float M1n = (l1 == 0) ? NEG2 : M1g;
        float I1n = (l1 == 0) ? NEG2 : I1g;

        // ---- slot2: cell (l2, k2); neighbor is own (old) slot1 ----
        float M2g = e2 + lse3(aMM2 + pM1, aIM2 + pI1, aDM2 + pD1);
        float I2g = laexp2(aMI2 + cM2, aII2 + cI2);
        float D2n = laexp2(aMD2 + cM1, aDD2 + cD1);
        float M2n = (l2 == 0) ? NEG2 : M2g;
        float I2n = (l2 == 0) ? NEG2 : I2g;

        // ---- k=0 column, cell (t, 0): M=NEG for l>=1, D=NEG always ----
        float k0In = laexp2(aMI0 + k0cM, aII0 + k0cI);
        k0pM = k0cM; k0pI = k0cI; k0cM = NEG2; k0cI = k0In;

        // unconditional rotation (enables cross-iteration register renaming)
        pM2 = cM2; pI2 = cI2; pD2 = cD2; cM2 = M2n; cI2 = I2n; cD2 = D2n;
        pM1 = cM1; pI1 = cI1; pD1 = cD1; cM1 = M1n; cI1 = I1n; cD1 = D1n;
        cprev = c1;
    }

    // lane 31 slot2 holds (M, I, D) at (L, K); broadcast to all lanes
    const float MF = __shfl_sync(FULLMASK, cM2, 31);
    const float IF = __shfl_sync(FULLMASK, cI2, 31);
    const float DF = __shfl_sync(FULLMASK, cD2, 31);
    const float lse = lse3(MF + a[K * 7 + 0] * LOG2E,
                           IF + a[K * 7 + 3] * LOG2E,
                           DF + a[K * 7 + 5] * LOG2E);
    const float nll = -lse * LN2;

    // KLD term: -0.5 * sum_e (1 + lv - mu^2 - exp(lv))
    float term = 0.0f;
    if (lane < 16) {
        const float mu = mus[b * 16 + lane];
        const float lv = logvars[b * 16 + lane];
        term = 1.0f + lv - mu * mu - expf(lv);
    }
#pragma unroll
    for (int o = 16; o > 0; o >>= 1) term += __shfl_xor_sync(FULLMASK, term, o);

    if (lane == 0) g_vb[b] = nll - 0.5f * term;

    // ---- last-block-done final reduction (deterministic fixed-order sum) ----
    __threadfence();
    unsigned int old = 0;
    if (lane == 0) old = atomicAdd(&g_cnt, 1u);
    old = __shfl_sync(FULLMASK, old, 0);
    if (old == gridDim.x - 1) {
        __threadfence();
        float s = 0.0f;
#pragma unroll
        for (int i = 0; i < 16; ++i) s += g_vb[lane + 32 * i];
#pragma unroll
        for (int o = 16; o > 0; o >>= 1) s += __shfl_xor_sync(FULLMASK, s, o);
        if (lane == 0) { out[0] = s * (1.0f / 512.0f); g_cnt = 0; }
    }
}

extern "C" void kernel_launch(void* const* d_in, const int* in_sizes, int n_in,
                              void* d_out, int out_size) {
    const int*   batch_input = (const int*)  d_in[0];
    const float* trans       = (const float*)d_in[1];
    const float* emisp       = (const float*)d_in[2];
    const float* mus         = (const float*)d_in[3];
    const float* logvars     = (const float*)d_in[4];
    (void)in_sizes; (void)n_in; (void)out_size;

    phmm_kernel<<<512, 32>>>(batch_input, trans, emisp, mus, logvars, (float*)d_out);
}

// round 5
// speedup vs baseline: 3.1584x; 1.0873x over previous
#include <cuda_runtime.h>

// Profile-HMM forward NLL + KLD, wavefront (anti-diagonal) formulation.
// 512 one-warp blocks. Lane owns k = 2*lane+1, 2*lane+2. Base-2 log domain.
// 2-term logaddexp uses m + e*P3(e) with e = 2^(-|x-y|)  (exact when one
// term dominates); 3-term (M recurrence) keeps MUFU lg2 accuracy.

#define FULLMASK 0xffffffffu
#define LOG2E 1.4426950408889634f
#define LN2   0.69314718055994531f
#define NEG2  (-144.26950408889634f)   /* -100 * log2(e) */

// degree-3 fit of log2(1+e)/e on [0,1] (Chebyshev-node interpolation)
#define LA_A0 1.442110f
#define LA_A1 (-0.701043f)
#define LA_A2 0.364460f
#define LA_A3 (-0.105873f)

__device__ float g_vb[512];
__device__ unsigned int g_cnt = 0;

__device__ __forceinline__ float fexp2(float x) {
    float r; asm("ex2.approx.f32 %0, %1;" : "=f"(r) : "f"(x)); return r;
}
__device__ __forceinline__ float flog2(float x) {
    float r; asm("lg2.approx.f32 %0, %1;" : "=f"(r) : "f"(x)); return r;
}
// base-2 logaddexp via polynomial: m + e*P3(e), e = 2^(-|x-y|) in (0,1]
__device__ __forceinline__ float laexp2p(float x, float y) {
    float m = fmaxf(x, y);
    float e = fexp2(-fabsf(x - y));
    float t = fmaf(e, LA_A3, LA_A2);
    t = fmaf(e, t, LA_A1);
    t = fmaf(e, t, LA_A0);
    return fmaf(e, t, m);
}
// base-2 3-way logsumexp (full MUFU accuracy for the M recurrence)
__device__ __forceinline__ float lse3(float x, float y, float z) {
    float m = fmaxf(fmaxf(x, y), z);
    return m + flog2(fexp2(x - m) + fexp2(y - m) + fexp2(z - m));
}

__global__ void __launch_bounds__(32) phmm_kernel(
    const int*   __restrict__ binput,    // (B, 256)
    const float* __restrict__ trans,     // (B, 65, 7)
    const float* __restrict__ emis,      // (B, 64, 4)
    const float* __restrict__ mus,       // (B, 16)
    const float* __restrict__ logvars,   // (B, 16)
    float*       __restrict__ out)
{
    constexpr int L = 256;
    constexpr int K = 64;
    const int b    = blockIdx.x;
    const int lane = threadIdx.x;

    __shared__ int   s_co[320];          // symbol*32 (element offset into e*sh)
    __shared__ float e1sh[128];          // [4 symbols][32 lanes] -- bank = lane
    __shared__ float e2sh[128];

    const int* bi = binput + b * L;
#pragma unroll
    for (int i = 0; i < L / 32; ++i) s_co[lane + 32 * i] = bi[lane + 32 * i] << 5;
    s_co[256 + lane] = 0;
    s_co[288 + lane] = 0;

    const float* a  = trans + b * 65 * 7;
    const float* em = emis  + b * 64 * 4;

    const int k1 = 2 * lane + 1;                // slot1 owns k1, slot2 owns k1+1
    const float* r0 = a + (k1 - 1) * 7;         // transition row k1-1
    const float* r1 = r0 + 7;                   // row k1   (= row k2-1)
    const float* r2 = r1 + 7;                   // row k2

    // indices: M2M=0, M2I=1, M2D=2, I2M=3, I2I=4, D2M=5, D2D=6
    // LOG_Q (base-2: -2) folded into aMI/aII.
    const float aMM1 = r0[0] * LOG2E, aMD1 = r0[2] * LOG2E;
    const float aIM1 = r0[3] * LOG2E, aDM1 = r0[5] * LOG2E, aDD1 = r0[6] * LOG2E;
    const float aMI1 = r1[1] * LOG2E - 2.0f, aII1 = r1[4] * LOG2E - 2.0f;
    const float aMM2 = r1[0] * LOG2E, aMD2 = r1[2] * LOG2E;
    const float aIM2 = r1[3] * LOG2E, aDM2 = r1[5] * LOG2E, aDD2 = r1[6] * LOG2E;
    const float aMI2 = r2[1] * LOG2E - 2.0f, aII2 = r2[4] * LOG2E - 2.0f;
    const float aMI0 = a[1]  * LOG2E - 2.0f, aII0 = a[4]  * LOG2E - 2.0f;  // row 0

#pragma unroll
    for (int c = 0; c < 4; ++c) {
        e1sh[c * 32 + lane] = em[(k1 - 1) * 4 + c] * LOG2E;
        e2sh[c * 32 + lane] = em[k1 * 4 + c] * LOG2E;
    }
    __syncwarp();

    // state registers: cur = this k's cell on diag t-1, prev = diag t-2
    float cM1 = NEG2, cI1 = NEG2, cD1 = NEG2, pM1 = NEG2, pI1 = NEG2, pD1 = NEG2;
    float cM2 = NEG2, cI2 = NEG2, cD2 = NEG2, pM2 = NEG2, pI2 = NEG2, pD2 = NEG2;
    // carried neighbor values (become q* = diag t-2 of column k-1)
    float qM = NEG2, qI = NEG2, qD = NEG2;
    // k=0 column: k0I = I(t-1, 0); mprev = M(t-1, 0)
    float k0I = NEG2, mprev = 0.0f;
    int off2 = s_co[0];

#pragma unroll 4
    for (int t = 1; t <= L + K; ++t) {
        // neighbor (k-1) values on diag t-1: lane-1's slot2 (or k=0 column)
        float nM = __shfl_up_sync(FULLMASK, cM2, 1);
        float nI = __shfl_up_sync(FULLMASK, cI2, 1);
        float nD = __shfl_up_sync(FULLMASK, cD2, 1);
        if (lane == 0) { nM = mprev; nI = k0I; nD = NEG2; }

        // k=0 column update: I(t,0) = laexp(aMI0 + M(t-1,0), aII0 + I(t-1,0))
        k0I = laexp2p(aMI0 + mprev, aII0 + k0I);
        mprev = NEG2;

        const int l1 = t - k1;
        const int off1 = s_co[max(l1 - 1, 0)];
        const float e1 = e1sh[off1 + lane];
        const float e2 = e2sh[off2 + lane];

        // ---- slot1: cell (l1, k1) ----
        float M1g = e1 + lse3(aMM1 + qM, aIM1 + qI, aDM1 + qD);
        float I1g = laexp2p(aMI1 + cM1, aII1 + cI1);
        float D1n = laexp2p(aMD1 + nM, aDD1 + nD);
        float M1n = (l1 == 0) ? NEG2 : M1g;
        float I1n = (l1 == 0) ? NEG2 : I1g;

        // ---- slot2: cell (l1-1, k1+1); q-cell = p*1, n-cell = c*1 ----
        float M2g = e2 + lse3(aMM2 + pM1, aIM2 + pI1, aDM2 + pD1);
        float I2g = laexp2p(aMI2 + cM2, aII2 + cI2);
        float D2n = laexp2p(aMD2 + cM1, aDD2 + cD1);
        float M2n = (l1 == 1) ? NEG2 : M2g;
        float I2n = (l1 == 1) ? NEG2 : I2g;

        // unconditional rotation + carries
        pM2 = cM2; pI2 = cI2; pD2 = cD2; cM2 = M2n; cI2 = I2n; cD2 = D2n;
        pM1 = cM1; pI1 = cI1; pD1 = cD1; cM1 = M1n; cI1 = I1n; cD1 = D1n;
        qM = nM; qI = nI; qD = nD; off2 = off1;
    }

    // lane 31 slot2 holds (M, I, D) at (L, K); broadcast to all lanes
    const float MF = __shfl_sync(FULLMASK, cM2, 31);
    const float IF = __shfl_sync(FULLMASK, cI2, 31);
    const float DF = __shfl_sync(FULLMASK, cD2, 31);
    const float lse = lse3(MF + a[K * 7 + 0] * LOG2E,
                           IF + a[K * 7 + 3] * LOG2E,
                           DF + a[K * 7 + 5] * LOG2E);
    const float nll = -lse * LN2;

    // KLD term: -0.5 * sum_e (1 + lv - mu^2 - exp(lv))
    float term = 0.0f;
    if (lane < 16) {
        const float mu = mus[b * 16 + lane];
        const float lv = logvars[b * 16 + lane];
        term = 1.0f + lv - mu * mu - expf(lv);
    }
#pragma unroll
    for (int o = 16; o > 0; o >>= 1) term += __shfl_xor_sync(FULLMASK, term, o);

    if (lane == 0) g_vb[b] = nll - 0.5f * term;

    // ---- last-block-done final reduction (deterministic fixed-order sum) ----
    __threadfence();
    unsigned int old = 0;
    if (lane == 0) old = atomicAdd(&g_cnt, 1u);
    old = __shfl_sync(FULLMASK, old, 0);
    if (old == gridDim.x - 1) {
        __threadfence();
        float s = 0.0f;
#pragma unroll
        for (int i = 0; i < 16; ++i) s += g_vb[lane + 32 * i];
#pragma unroll
        for (int o = 16; o > 0; o >>= 1) s += __shfl_xor_sync(FULLMASK, s, o);
        if (lane == 0) { out[0] = s * (1.0f / 512.0f); g_cnt = 0; }
    }
}

extern "C" void kernel_launch(void* const* d_in, const int* in_sizes, int n_in,
                              void* d_out, int out_size) {
    const int*   batch_input = (const int*)  d_in[0];
    const float* trans       = (const float*)d_in[1];
    const float* emisp       = (const float*)d_in[2];
    const float* mus         = (const float*)d_in[3];
    const float* logvars     = (const float*)d_in[4];
    (void)in_sizes; (void)n_in; (void)out_size;

    phmm_kernel<<<512, 32>>>(batch_input, trans, emisp, mus, logvars, (float*)d_out);
}

// round 6
// speedup vs baseline: 4.9898x; 1.5798x over previous
#include <cuda_runtime.h>

// Profile-HMM forward NLL + KLD -- wavefront, SCALED LINEAR DOMAIN.
// 512 one-warp blocks. Lane owns k = 2*lane+1, 2*lane+2. All probabilities
// kept linear; warp-uniform power-of-2 rescale every 4 diagonals keeps
// magnitudes in range (Sacc accumulates the log2 scale). The finite NEG=-100
// boundary is a real value 'inj' = e^-100 * 2^Sacc, rescaled with the states.
// Per cell: M = e*(aMM*qM+aIM*qI+aDM*qD), I = aMI*cM+aII*cI, D = aMD*nM+aDD*nD.
// Zero MUFU in the main loop.

#define FULLMASK 0xffffffffu
#define LN2 0.69314718055994531f

__device__ float g_vb[512];
__device__ unsigned int g_cnt = 0;

__global__ void __launch_bounds__(32) phmm_kernel(
    const int*   __restrict__ binput,    // (B, 256)
    const float* __restrict__ trans,     // (B, 65, 7) log-probs (nats)
    const float* __restrict__ emis,      // (B, 64, 4) log-probs (nats)
    const float* __restrict__ mus,       // (B, 16)
    const float* __restrict__ logvars,   // (B, 16)
    float*       __restrict__ out)
{
    constexpr int L = 256;
    constexpr int K = 64;
    const int b    = blockIdx.x;
    const int lane = threadIdx.x;

    __shared__ int   s_co[320];          // symbol*32 (offset into e*sh)
    __shared__ float e1sh[128];          // [4 symbols][32 lanes], bank = lane
    __shared__ float e2sh[128];

    const int* bi = binput + b * L;
#pragma unroll
    for (int i = 0; i < L / 32; ++i) s_co[lane + 32 * i] = bi[lane + 32 * i] << 5;
    s_co[256 + lane] = 0;
    s_co[288 + lane] = 0;

    const float* a  = trans + b * 65 * 7;
    const float* em = emis  + b * 64 * 4;

    const int k1 = 2 * lane + 1;                // slot1 owns k1, slot2 owns k1+1
    const float* r0 = a + (k1 - 1) * 7;         // transition row k1-1
    const float* r1 = r0 + 7;                   // row k1 (= row k2-1)
    const float* r2 = r1 + 7;                   // row k2

    // indices: M2M=0, M2I=1, M2D=2, I2M=3, I2I=4, D2M=5, D2D=6
    // LOG_Q (q=0.25) folded into aMI/aII.
    const float aMM1 = expf(r0[0]), aMD1 = expf(r0[2]);
    const float aIM1 = expf(r0[3]), aDM1 = expf(r0[5]), aDD1 = expf(r0[6]);
    const float aMI1 = 0.25f * expf(r1[1]), aII1 = 0.25f * expf(r1[4]);
    const float aMM2 = expf(r1[0]), aMD2 = expf(r1[2]);
    const float aIM2 = expf(r1[3]), aDM2 = expf(r1[5]), aDD2 = expf(r1[6]);
    const float aMI2 = 0.25f * expf(r2[1]), aII2 = 0.25f * expf(r2[4]);
    const float aMI0 = 0.25f * expf(a[1]),  aII0 = 0.25f * expf(a[4]);   // row 0

#pragma unroll
    for (int c = 0; c < 4; ++c) {
        e1sh[c * 32 + lane] = expf(em[(k1 - 1) * 4 + c]);
        e2sh[c * 32 + lane] = expf(em[k1 * 4 + c]);
    }
    __syncwarp();

    // loop-carried state (all scaled by 2^Sacc relative to absolute probs)
    float cM1 = 0.f, cI1 = 0.f, cD1 = 0.f, pM1 = 0.f, pI1 = 0.f, pD1 = 0.f;
    float cM2 = 0.f, cI2 = 0.f, cD2 = 0.f, pM2 = 0.f, pI2 = 0.f, pD2 = 0.f;
    float qM = 0.f, qI = 0.f, qD = 0.f;      // carried neighbor diag t-2 values
    float inj   = exp2f(-84.26950408889634f);   // e^-100 * 2^60  (NEG boundary)
    float k0I   = inj;                          // I(0,0) = NEG
    float mprev = 1.152921504606847e18f;        // M(0,0) = 1 * 2^60
    int   Sacc  = 60;
    int   off2  = s_co[0];

#pragma unroll 4
    for (int t = 1; t <= L + K; ++t) {
        // neighbor (k-1) values on diag t-1: lane-1's slot2 (or k=0 column)
        float nM = __shfl_up_sync(FULLMASK, cM2, 1);
        float nI = __shfl_up_sync(FULLMASK, cI2, 1);
        float nD = __shfl_up_sync(FULLMASK, cD2, 1);
        if (lane == 0) { nM = mprev; nI = k0I; nD = inj; }

        // k=0 column: I(t,0) = q*(aMI0*M(t-1,0) + aII0*I(t-1,0)); M(t,0)=NEG
        k0I = fmaf(aII0, k0I, aMI0 * mprev);
        mprev = inj;

        const int l1 = t - k1;
        const int off1 = s_co[max(l1 - 1, 0)];
        const float e1 = e1sh[off1 + lane];
        const float e2 = e2sh[off2 + lane];

        // ---- slot1: cell (l1, k1) ----
        float M1g = e1 * fmaf(aDM1, qD, fmaf(aIM1, qI, aMM1 * qM));
        float I1g = fmaf(aII1, cI1, aMI1 * cM1);
        float D1n = fmaf(aDD1, nD, aMD1 * nM);
        float M1n = (l1 == 0) ? inj : M1g;
        float I1n = (l1 == 0) ? inj : I1g;

        // ---- slot2: cell (l1-1, k1+1); q-cell = p*1, n-cell = c*1 ----
        float M2g = e2 * fmaf(aDM2, pD1, fmaf(aIM2, pI1, aMM2 * pM1));
        float I2g = fmaf(aII2, cI2, aMI2 * cM2);
        float D2n = fmaf(aDD2, cD1, aMD2 * cM1);
        float M2n = (l1 == 1) ? inj : M2g;
        float I2n = (l1 == 1) ? inj : I2g;

        // unconditional rotation + carries
        pM2 = cM2; pI2 = cI2; pD2 = cD2; cM2 = M2n; cI2 = I2n; cD2 = D2n;
        pM1 = cM1; pI1 = cI1; pD1 = cD1; cM1 = M1n; cI1 = I1n; cD1 = D1n;
        qM = nM; qI = nI; qD = nD; off2 = off1;

        // ---- warp-uniform power-of-2 rescale every 4 diagonals ----
        if ((t & 3) == 0) {
            float m = fmaxf(fmaxf(cM1, cM2), fmaxf(cI1, cI2));
            m = fmaxf(m, fmaxf(cD1, cD2));
            m = fmaxf(m, k0I);
#pragma unroll
            for (int o = 16; o > 0; o >>= 1)
                m = fmaxf(m, __shfl_xor_sync(FULLMASK, m, o));
            const int E  = (__float_as_int(m) >> 23) & 0xFF;   // biased exponent
            int se = 187 - E;                                  // 60 - (E - 127)
            se = min(se, 126);
            const float sc = __int_as_float((se + 127) << 23); // 2^se
            cM1 *= sc; cI1 *= sc; cD1 *= sc; pM1 *= sc; pI1 *= sc; pD1 *= sc;
            cM2 *= sc; cI2 *= sc; cD2 *= sc; pM2 *= sc; pI2 *= sc; pD2 *= sc;
            qM  *= sc; qI  *= sc; qD  *= sc; k0I *= sc; mprev *= sc; inj *= sc;
            Sacc += se;
        }
    }

    // lane 31 slot2 holds (M, I, D) at (L, K); broadcast to all lanes
    const float MF = __shfl_sync(FULLMASK, cM2, 31);
    const float IF = __shfl_sync(FULLMASK, cI2, 31);
    const float DF = __shfl_sync(FULLMASK, cD2, 31);
    const float fM = expf(a[K * 7 + 0]);
    const float fI = expf(a[K * 7 + 3]);
    const float fD = expf(a[K * 7 + 5]);
    const float sum = fmaf(fD, DF, fmaf(fI, IF, fM * MF));
    const float nll = -(log2f(sum) - (float)Sacc) * LN2;

    // KLD term: -0.5 * sum_e (1 + lv - mu^2 - exp(lv))
    float term = 0.0f;
    if (lane < 16) {
        const float mu = mus[b * 16 + lane];
        const float lv = logvars[b * 16 + lane];
        term = 1.0f + lv - mu * mu - expf(lv);
    }
#pragma unroll
    for (int o = 16; o > 0; o >>= 1) term += __shfl_xor_sync(FULLMASK, term, o);

    if (lane == 0) g_vb[b] = nll - 0.5f * term;

    // ---- last-block-done final reduction (deterministic fixed-order sum) ----
    __threadfence();
    unsigned int old = 0;
    if (lane == 0) old = atomicAdd(&g_cnt, 1u);
    old = __shfl_sync(FULLMASK, old, 0);
    if (old == gridDim.x - 1) {
        __threadfence();
        float s = 0.0f;
#pragma unroll
        for (int i = 0; i < 16; ++i) s += g_vb[lane + 32 * i];
#pragma unroll
        for (int o = 16; o > 0; o >>= 1) s += __shfl_xor_sync(FULLMASK, s, o);
        if (lane == 0) { out[0] = s * (1.0f / 512.0f); g_cnt = 0; }
    }
}

extern "C" void kernel_launch(void* const* d_in, const int* in_sizes, int n_in,
                              void* d_out, int out_size) {
    const int*   batch_input = (const int*)  d_in[0];
    const float* trans       = (const float*)d_in[1];
    const float* emisp       = (const float*)d_in[2];
    const float* mus         = (const float*)d_in[3];
    const float* logvars     = (const float*)d_in[4];
    (void)in_sizes; (void)n_in; (void)out_size;

    phmm_kernel<<<512, 32>>>(batch_input, trans, emisp, mus, logvars, (float*)d_out);
}

// round 8
// speedup vs baseline: 6.4685x; 1.2964x over previous
#include <cuda_runtime.h>

// Profile-HMM forward NLL + KLD -- wavefront, scaled linear domain.
// 512 one-warp blocks. Lane owns k = 2*lane+1, 2*lane+2. Probabilities linear;
// power-of-2 rescale every 4 diagonals (lossless). The warp max uses
// redux.sync.max.u32 (positive floats order-isomorphic to u32), and the scale
// is applied ONE WINDOW LATE so the reduction latency is off the critical
// path. States are sub-stochastic (never grow), so se >= 0 and a one-window
// stale scale is safe within float range (anchor 2^60, >180 bits headroom).

#define FULLMASK 0xffffffffu
#define LN2 0.69314718055994531f

__device__ float g_vb[512];
__device__ unsigned int g_cnt = 0;

__device__ __forceinline__ unsigned warp_max_u32(unsigned v) {
    unsigned r;
    asm volatile("redux.sync.max.u32 %0, %1, 0xffffffff;" : "=r"(r) : "r"(v));
    return r;
}

__global__ void __launch_bounds__(32) phmm_kernel(
    const int*   __restrict__ binput,    // (B, 256)
    const float* __restrict__ trans,     // (B, 65, 7) log-probs (nats)
    const float* __restrict__ emis,      // (B, 64, 4) log-probs (nats)
    const float* __restrict__ mus,       // (B, 16)
    const float* __restrict__ logvars,   // (B, 16)
    float*       __restrict__ out)
{
    constexpr int L = 256;
    constexpr int K = 64;
    const int b    = blockIdx.x;
    const int lane = threadIdx.x;

    __shared__ int   s_co[320];          // symbol*32 (offset into e*sh)
    __shared__ float e1sh[128];          // [4 symbols][32 lanes], bank = lane
    __shared__ float e2sh[128];

    const int* bi = binput + b * L;
#pragma unroll
    for (int i = 0; i < L / 32; ++i) s_co[lane + 32 * i] = bi[lane + 32 * i] << 5;
    s_co[256 + lane] = 0;
    s_co[288 + lane] = 0;

    const float* a  = trans + b * 65 * 7;
    const float* em = emis  + b * 64 * 4;

    const int k1 = 2 * lane + 1;                // slot1 owns k1, slot2 owns k1+1
    const float* r0 = a + (k1 - 1) * 7;         // transition row k1-1
    const float* r1 = r0 + 7;                   // row k1 (= row k2-1)
    const float* r2 = r1 + 7;                   // row k2

    // indices: M2M=0, M2I=1, M2D=2, I2M=3, I2I=4, D2M=5, D2D=6
    // LOG_Q (q=0.25) folded into aMI/aII.
    const float aMM1 = expf(r0[0]), aMD1 = expf(r0[2]);
    const float aIM1 = expf(r0[3]), aDM1 = expf(r0[5]), aDD1 = expf(r0[6]);
    const float aMI1 = 0.25f * expf(r1[1]), aII1 = 0.25f * expf(r1[4]);
    const float aMM2 = expf(r1[0]), aMD2 = expf(r1[2]);
    const float aIM2 = expf(r1[3]), aDM2 = expf(r1[5]), aDD2 = expf(r1[6]);
    const float aMI2 = 0.25f * expf(r2[1]), aII2 = 0.25f * expf(r2[4]);
    const float aMI0 = 0.25f * expf(a[1]),  aII0 = 0.25f * expf(a[4]);   // row 0

#pragma unroll
    for (int c = 0; c < 4; ++c) {
        e1sh[c * 32 + lane] = expf(em[(k1 - 1) * 4 + c]);
        e2sh[c * 32 + lane] = expf(em[k1 * 4 + c]);
    }
    __syncwarp();

    // loop-carried state (all scaled by 2^Sacc relative to absolute probs)
    float cM1 = 0.f, cI1 = 0.f, cD1 = 0.f, pM1 = 0.f, pI1 = 0.f, pD1 = 0.f;
    float cM2 = 0.f, cI2 = 0.f, cD2 = 0.f, pM2 = 0.f, pI2 = 0.f, pD2 = 0.f;
    float qM = 0.f, qI = 0.f, qD = 0.f;      // carried neighbor diag t-2 values
    float inj   = exp2f(-84.26950408889634f);   // e^-100 * 2^60  (NEG boundary)
    float k0I   = inj;                          // I(0,0) = NEG
    float mprev = 1.152921504606847e18f;        // M(0,0) = 1 * 2^60
    int   Sacc  = 60;
    int   off2  = s_co[0];
    // deferred rescale: scale computed from window t, applied at window t+1
    float sc_ap = 1.0f;
    int   se_ap = 0;

#pragma unroll 4
    for (int t = 1; t <= L + K; ++t) {
        // neighbor (k-1) values on diag t-1: lane-1's slot2 (or k=0 column)
        float nM = __shfl_up_sync(FULLMASK, cM2, 1);
        float nI = __shfl_up_sync(FULLMASK, cI2, 1);
        float nD = __shfl_up_sync(FULLMASK, cD2, 1);
        if (lane == 0) { nM = mprev; nI = k0I; nD = inj; }

        // k=0 column: I(t,0) = q*(aMI0*M(t-1,0) + aII0*I(t-1,0)); M(t,0)=NEG
        k0I = fmaf(aII0, k0I, aMI0 * mprev);
        mprev = inj;

        const int l1 = t - k1;
        const int off1 = s_co[max(l1 - 1, 0)];
        const float e1 = e1sh[off1 + lane];
        const float e2 = e2sh[off2 + lane];

        // ---- slot1: cell (l1, k1) ----
        float M1g = e1 * fmaf(aDM1, qD, fmaf(aIM1, qI, aMM1 * qM));
        float I1g = fmaf(aII1, cI1, aMI1 * cM1);
        float D1n = fmaf(aDD1, nD, aMD1 * nM);
        float M1n = (l1 == 0) ? inj : M1g;
        float I1n = (l1 == 0) ? inj : I1g;

        // ---- slot2: cell (l1-1, k1+1); q-cell = p*1, n-cell = c*1 ----
        float M2g = e2 * fmaf(aDM2, pD1, fmaf(aIM2, pI1, aMM2 * pM1));
        float I2g = fmaf(aII2, cI2, aMI2 * cM2);
        float D2n = fmaf(aDD2, cD1, aMD2 * cM1);
        float M2n = (l1 == 1) ? inj : M2g;
        float I2n = (l1 == 1) ? inj : I2g;

        // unconditional rotation + carries
        pM2 = cM2; pI2 = cI2; pD2 = cD2; cM2 = M2n; cI2 = I2n; cD2 = D2n;
        pM1 = cM1; pI1 = cI1; pD1 = cD1; cM1 = M1n; cI1 = I1n; cD1 = D1n;
        qM = nM; qI = nI; qD = nD; off2 = off1;

        // ---- deferred power-of-2 rescale every 4 diagonals ----
        if ((t & 3) == 0) {
            // apply the scale computed at the PREVIOUS window (latency hidden)
            cM1 *= sc_ap; cI1 *= sc_ap; cD1 *= sc_ap;
            pM1 *= sc_ap; pI1 *= sc_ap; pD1 *= sc_ap;
            cM2 *= sc_ap; cI2 *= sc_ap; cD2 *= sc_ap;
            pM2 *= sc_ap; pI2 *= sc_ap; pD2 *= sc_ap;
            qM  *= sc_ap; qI  *= sc_ap; qD  *= sc_ap;
            k0I *= sc_ap; mprev *= sc_ap; inj *= sc_ap;
            Sacc += se_ap;
            // start the next window's reduction (consumed 4 iters from now)
            float m = fmaxf(fmaxf(cM1, cM2), fmaxf(cI1, cI2));
            m = fmaxf(m, fmaxf(cD1, cD2));
            m = fmaxf(m, k0I);
            const unsigned mu32 = warp_max_u32(__float_as_uint(m));
            const int E = (int)(mu32 >> 23) & 0xFF;            // biased exponent
            int se = 187 - E;                                  // 60 - (E - 127)
            se = min(max(se, 0), 120);
            se_ap = se;
            sc_ap = __int_as_float((se + 127) << 23);          // 2^se (exact)
        }
    }

    // lane 31 slot2 holds (M, I, D) at (L, K); broadcast to all lanes
    const float MF = __shfl_sync(FULLMASK, cM2, 31);
    const float IF = __shfl_sync(FULLMASK, cI2, 31);
    const float DF = __shfl_sync(FULLMASK, cD2, 31);
    const float fM = expf(a[K * 7 + 0]);
    const float fI = expf(a[K * 7 + 3]);
    const float fD = expf(a[K * 7 + 5]);
    const float sum = fmaf(fD, DF, fmaf(fI, IF, fM * MF));
    const float nll = -(log2f(sum) - (float)Sacc) * LN2;

    // KLD term: -0.5 * sum_e (1 + lv - mu^2 - exp(lv))
    float term = 0.0f;
    if (lane < 16) {
        const float mu = mus[b * 16 + lane];
        const float lv = logvars[b * 16 + lane];
        term = 1.0f + lv - mu * mu - expf(lv);
    }
#pragma unroll
    for (int o = 16; o > 0; o >>= 1) term += __shfl_xor_sync(FULLMASK, term, o);

    if (lane == 0) g_vb[b] = nll - 0.5f * term;

    // ---- last-block-done final reduction (deterministic fixed-order sum) ----
    __threadfence();
    unsigned int old = 0;
    if (lane == 0) old = atomicAdd(&g_cnt, 1u);
    old = __shfl_sync(FULLMASK, old, 0);
    if (old == gridDim.x - 1) {
        __threadfence();
        float s = 0.0f;
#pragma unroll
        for (int i = 0; i < 16; ++i) s += g_vb[lane + 32 * i];
#pragma unroll
        for (int o = 16; o > 0; o >>= 1) s += __shfl_xor_sync(FULLMASK, s, o);
        if (lane == 0) { out[0] = s * (1.0f / 512.0f); g_cnt = 0; }
    }
}

extern "C" void kernel_launch(void* const* d_in, const int* in_sizes, int n_in,
                              void* d_out, int out_size) {
    const int*   batch_input = (const int*)  d_in[0];
    const float* trans       = (const float*)d_in[1];
    const float* emisp       = (const float*)d_in[2];
    const float* mus         = (const float*)d_in[3];
    const float* logvars     = (const float*)d_in[4];
    (void)in_sizes; (void)n_in; (void)out_size;

    phmm_kernel<<<512, 32>>>(batch_input, trans, emisp, mus, logvars, (float*)d_out);
}

// round 9
// speedup vs baseline: 6.7712x; 1.0468x over previous
#include <cuda_runtime.h>

// Profile-HMM forward NLL + KLD -- wavefront, scaled linear domain.
// 512 one-warp blocks. Lane owns k = 2*lane+1, 2*lane+2. Probabilities linear;
// deferred power-of-2 rescale every 4 diagonals via redux.sync (lossless).
// Emission lookups are software-pipelined (depth 2) and packed: at iter t we
// prefetch the s_co offset for t+2 and the float2 emission pack for t+1, so
// the two-level LDS chain is fully off the critical path.

#define FULLMASK 0xffffffffu
#define LN2 0.69314718055994531f

__device__ float g_vb[512];
__device__ unsigned int g_cnt = 0;

__device__ __forceinline__ unsigned warp_max_u32(unsigned v) {
    unsigned r;
    asm volatile("redux.sync.max.u32 %0, %1, 0xffffffff;" : "=r"(r) : "r"(v));
    return r;
}

__global__ void __launch_bounds__(32) phmm_kernel(
    const int*   __restrict__ binput,    // (B, 256)
    const float* __restrict__ trans,     // (B, 65, 7) log-probs (nats)
    const float* __restrict__ emis,      // (B, 64, 4) log-probs (nats)
    const float* __restrict__ mus,       // (B, 16)
    const float* __restrict__ logvars,   // (B, 16)
    float*       __restrict__ out)
{
    constexpr int L = 256;
    constexpr int K = 64;
    const int b    = blockIdx.x;
    const int lane = threadIdx.x;

    // s_co_p: 64 front-pad + 256 symbols + back-pad, value = symbol*32
    __shared__ int    s_co_p[416];
    __shared__ float2 ep[128];           // [4 symbols][32 lanes] {e1, e2}

    const int* bi = binput + b * L;
#pragma unroll
    for (int i = 0; i < 13; ++i) {
        const int idx = lane + 32 * i;   // covers [0, 416)
        int v = 0;
        if (idx >= 64 && idx < 320) v = bi[idx - 64] << 5;
        s_co_p[idx] = v;
    }

    const float* a  = trans + b * 65 * 7;
    const float* em = emis  + b * 64 * 4;

    const int k1 = 2 * lane + 1;                // slot1 owns k1, slot2 owns k1+1
    const float* r0 = a + (k1 - 1) * 7;         // transition row k1-1
    const float* r1 = r0 + 7;                   // row k1 (= row k2-1)
    const float* r2 = r1 + 7;                   // row k2

    // indices: M2M=0, M2I=1, M2D=2, I2M=3, I2I=4, D2M=5, D2D=6
    // LOG_Q (q=0.25) folded into aMI/aII.
    const float aMM1 = expf(r0[0]), aMD1 = expf(r0[2]);
    const float aIM1 = expf(r0[3]), aDM1 = expf(r0[5]), aDD1 = expf(r0[6]);
    const float aMI1 = 0.25f * expf(r1[1]), aII1 = 0.25f * expf(r1[4]);
    const float aMM2 = expf(r1[0]), aMD2 = expf(r1[2]);
    const float aIM2 = expf(r1[3]), aDM2 = expf(r1[5]), aDD2 = expf(r1[6]);
    const float aMI2 = 0.25f * expf(r2[1]), aII2 = 0.25f * expf(r2[4]);
    const float aMI0 = 0.25f * expf(a[1]),  aII0 = 0.25f * expf(a[4]);   // row 0

#pragma unroll
    for (int c = 0; c < 4; ++c)
        ep[c * 32 + lane] = make_float2(expf(em[(k1 - 1) * 4 + c]),
                                        expf(em[k1 * 4 + c]));
    __syncwarp();

    // loop-carried state (all scaled by 2^Sacc relative to absolute probs)
    float cM1 = 0.f, cI1 = 0.f, cD1 = 0.f, pM1 = 0.f, pI1 = 0.f, pD1 = 0.f;
    float cM2 = 0.f, cI2 = 0.f, cD2 = 0.f, pM2 = 0.f, pI2 = 0.f, pD2 = 0.f;
    float qM = 0.f, qI = 0.f, qD = 0.f;      // carried neighbor diag t-2 values
    float inj   = exp2f(-84.26950408889634f);   // e^-100 * 2^60  (NEG boundary)
    float k0I   = inj;                          // I(0,0) = NEG
    float mprev = 1.152921504606847e18f;        // M(0,0) = 1 * 2^60
    int   Sacc  = 60;
    // deferred rescale: scale computed from window t, applied at window t+1
    float sc_ap = 1.0f;
    int   se_ap = 0;

    // emission pipeline priming (t=1): P = pack for e1(1); off_p feeds P(2)
    int    off_p = s_co_p[65 - k1];     // s_co index for e1(2)
    float2 P     = ep[s_co_p[64 - k1] + lane];
    float  e2c   = 0.0f;                // e2(1) is don't-care (cell dead)

#pragma unroll 4
    for (int t = 1; t <= L + K; ++t) {
        // neighbor (k-1) values on diag t-1: lane-1's slot2 (or k=0 column)
        float nM = __shfl_up_sync(FULLMASK, cM2, 1);
        float nI = __shfl_up_sync(FULLMASK, cI2, 1);
        float nD = __shfl_up_sync(FULLMASK, cD2, 1);
        if (lane == 0) { nM = mprev; nI = k0I; nD = inj; }

        // k=0 column: I(t,0) = q*(aMI0*M(t-1,0) + aII0*I(t-1,0)); M(t,0)=NEG
        k0I = fmaf(aII0, k0I, aMI0 * mprev);
        mprev = inj;

        // consume pipelined emissions; issue next prefetches (latency hidden)
        const float e1 = P.x;
        const float e2 = e2c;
        e2c = P.y;
        P = ep[off_p + lane];            // pack for iter t+1
        off_p = s_co_p[t - k1 + 65];     // s_co offset for iter t+2

        const int l1 = t - k1;

        // ---- slot1: cell (l1, k1) ----
        float M1g = e1 * fmaf(aDM1, qD, fmaf(aIM1, qI, aMM1 * qM));
        float I1g = fmaf(aII1, cI1, aMI1 * cM1);
        float D1n = fmaf(aDD1, nD, aMD1 * nM);
        float M1n = (l1 == 0) ? inj : M1g;
        float I1n = (l1 == 0) ? inj : I1g;

        // ---- slot2: cell (l1-1, k1+1); q-cell = p*1, n-cell = c*1 ----
        float M2g = e2 * fmaf(aDM2, pD1, fmaf(aIM2, pI1, aMM2 * pM1));
        float I2g = fmaf(aII2, cI2, aMI2 * cM2);
        float D2n = fmaf(aDD2, cD1, aMD2 * cM1);
        float M2n = (l1 == 1) ? inj : M2g;
        float I2n = (l1 == 1) ? inj : I2g;

        // unconditional rotation + carries
        pM2 = cM2; pI2 = cI2; pD2 = cD2; cM2 = M2n; cI2 = I2n; cD2 = D2n;
        pM1 = cM1; pI1 = cI1; pD1 = cD1; cM1 = M1n; cI1 = I1n; cD1 = D1n;
        qM = nM; qI = nI; qD = nD;

        // ---- deferred power-of-2 rescale every 4 diagonals ----
        if ((t & 3) == 0) {
            // apply the scale computed at the PREVIOUS window (latency hidden)
            cM1 *= sc_ap; cI1 *= sc_ap; cD1 *= sc_ap;
            pM1 *= sc_ap; pI1 *= sc_ap; pD1 *= sc_ap;
            cM2 *= sc_ap; cI2 *= sc_ap; cD2 *= sc_ap;
            pM2 *= sc_ap; pI2 *= sc_ap; pD2 *= sc_ap;
            qM  *= sc_ap; qI  *= sc_ap; qD  *= sc_ap;
            k0I *= sc_ap; mprev *= sc_ap; inj *= sc_ap;
            Sacc += se_ap;
            // start the next window's reduction (consumed 4 iters from now)
            float m = fmaxf(fmaxf(cM1, cM2), fmaxf(cI1, cI2));
            m = fmaxf(m, fmaxf(cD1, cD2));
            m = fmaxf(m, k0I);
            const unsigned mu32 = warp_max_u32(__float_as_uint(m));
            const int E = (int)(mu32 >> 23) & 0xFF;            // biased exponent
            int se = 187 - E;                                  // 60 - (E - 127)
            se = min(max(se, 0), 120);
            se_ap = se;
            sc_ap = __int_as_float((se + 127) << 23);          // 2^se (exact)
        }
    }

    // lane 31 slot2 holds (M, I, D) at (L, K); broadcast to all lanes
    const float MF = __shfl_sync(FULLMASK, cM2, 31);
    const float IF = __shfl_sync(FULLMASK, cI2, 31);
    const float DF = __shfl_sync(FULLMASK, cD2, 31);
    const float fM = expf(a[K * 7 + 0]);
    const float fI = expf(a[K * 7 + 3]);
    const float fD = expf(a[K * 7 + 5]);
    const float sum = fmaf(fD, DF, fmaf(fI, IF, fM * MF));
    const float nll = -(log2f(sum) - (float)Sacc) * LN2;

    // KLD term: -0.5 * sum_e (1 + lv - mu^2 - exp(lv))
    float term = 0.0f;
    if (lane < 16) {
        const float mu = mus[b * 16 + lane];
        const float lv = logvars[b * 16 + lane];
        term = 1.0f + lv - mu * mu - expf(lv);
    }
#pragma unroll
    for (int o = 16; o > 0; o >>= 1) term += __shfl_xor_sync(FULLMASK, term, o);

    if (lane == 0) g_vb[b] = nll - 0.5f * term;

    // ---- last-block-done final reduction (deterministic fixed-order sum) ----
    __threadfence();
    unsigned int old = 0;
    if (lane == 0) old = atomicAdd(&g_cnt, 1u);
    old = __shfl_sync(FULLMASK, old, 0);
    if (old == gridDim.x - 1) {
        __threadfence();
        float s = 0.0f;
#pragma unroll
        for (int i = 0; i < 16; ++i) s += g_vb[lane + 32 * i];
#pragma unroll
        for (int o = 16; o > 0; o >>= 1) s += __shfl_xor_sync(FULLMASK, s, o);
        if (lane == 0) { out[0] = s * (1.0f / 512.0f); g_cnt = 0; }
    }
}

extern "C" void kernel_launch(void* const* d_in, const int* in_sizes, int n_in,
                              void* d_out, int out_size) {
    const int*   batch_input = (const int*)  d_in[0];
    const float* trans       = (const float*)d_in[1];
    const float* emisp       = (const float*)d_in[2];
    const float* mus         = (const float*)d_in[3];
    const float* logvars     = (const float*)d_in[4];
    (void)in_sizes; (void)n_in; (void)out_size;

    phmm_kernel<<<512, 32>>>(batch_input, trans, emisp, mus, logvars, (float*)d_out);
}